// round 1
// baseline (speedup 1.0000x reference)
#include <cuda_runtime.h>
#include <cuda_bf16.h>
#include <cstdint>

// ---------------------------------------------------------------------------
// Problem constants
// ---------------------------------------------------------------------------
#define DIMC      256
#define HEADS     8
#define HEAD_DIM  32
#define HIDDEN    1024
#define SEQ       2048          // L*WW = 32*64
#define BATCH     2
#define ROWS_PER_STREAM (BATCH * SEQ)   // 4096
#define TOTAL_ROWS      (2 * ROWS_PER_STREAM) // 8192 (stream0 rows then stream1 rows)
#define STREAM_OFF      (ROWS_PER_STREAM * DIMC) // 4096*256 floats

// scale = HEAD_DIM^(-0.25)
#define QK_SCALE 0.42044820762685725f

// ---------------------------------------------------------------------------
// Scratch (device globals; no runtime allocation)
// ---------------------------------------------------------------------------
__device__ float g_n  [TOTAL_ROWS * DIMC];   // LN1 output  (n0 || n1)
__device__ float g_qk [TOTAL_ROWS * DIMC];   // qk proj * scale
__device__ float g_v  [TOTAL_ROWS * DIMC];   // v proj
__device__ float g_m  [TOTAL_ROWS * DIMC];   // attention outputs (unheaded)
__device__ float g_mm [TOTAL_ROWS * DIMC];   // merge proj
__device__ float g_cat[TOTAL_ROWS * 2 * DIMC]; // concat([x, m])
__device__ float g_h  [TOTAL_ROWS * HIDDEN]; // fc1+gelu
__device__ float g_t  [TOTAL_ROWS * DIMC];   // fc2 out

// ---------------------------------------------------------------------------
// LayerNorm: one warp per row of 256 floats
// ---------------------------------------------------------------------------
__global__ __launch_bounds__(256) void ln_kernel(
    const float* __restrict__ x, const float* __restrict__ w,
    const float* __restrict__ b, float* __restrict__ out)
{
    int warp = threadIdx.x >> 5, lane = threadIdx.x & 31;
    int row = blockIdx.x * 8 + warp;
    const float* xr = x + (size_t)row * DIMC;
    float v[8];
    float sum = 0.f;
#pragma unroll
    for (int i = 0; i < 8; i++) { v[i] = xr[lane + i * 32]; sum += v[i]; }
#pragma unroll
    for (int o = 16; o; o >>= 1) sum += __shfl_xor_sync(0xffffffffu, sum, o);
    float mean = sum * (1.f / 256.f);
    float vs = 0.f;
#pragma unroll
    for (int i = 0; i < 8; i++) { float d = v[i] - mean; vs += d * d; }
#pragma unroll
    for (int o = 16; o; o >>= 1) vs += __shfl_xor_sync(0xffffffffu, vs, o);
    float rstd = rsqrtf(vs * (1.f / 256.f) + 1e-5f);
    float* orow = out + (size_t)row * DIMC;
#pragma unroll
    for (int i = 0; i < 8; i++) {
        int c = lane + i * 32;
        orow[c] = (v[i] - mean) * rstd * w[c] + b[c];
    }
}

// ---------------------------------------------------------------------------
// Final: out = x + gamma * LayerNorm(t; ln2_w, ln2_b)
// ---------------------------------------------------------------------------
__global__ __launch_bounds__(256) void final_kernel(
    const float* __restrict__ t, const float* __restrict__ x,
    const float* __restrict__ w, const float* __restrict__ b,
    const float* __restrict__ gamma, float* __restrict__ out)
{
    int warp = threadIdx.x >> 5, lane = threadIdx.x & 31;
    int row = blockIdx.x * 8 + warp;
    const float* tr = t + (size_t)row * DIMC;
    const float* xr = x + (size_t)row * DIMC;
    float v[8];
    float sum = 0.f;
#pragma unroll
    for (int i = 0; i < 8; i++) { v[i] = tr[lane + i * 32]; sum += v[i]; }
#pragma unroll
    for (int o = 16; o; o >>= 1) sum += __shfl_xor_sync(0xffffffffu, sum, o);
    float mean = sum * (1.f / 256.f);
    float vs = 0.f;
#pragma unroll
    for (int i = 0; i < 8; i++) { float d = v[i] - mean; vs += d * d; }
#pragma unroll
    for (int o = 16; o; o >>= 1) vs += __shfl_xor_sync(0xffffffffu, vs, o);
    float rstd = rsqrtf(vs * (1.f / 256.f) + 1e-5f);
    float* orow = out + (size_t)row * DIMC;
#pragma unroll
    for (int i = 0; i < 8; i++) {
        int c = lane + i * 32;
        float ln = (v[i] - mean) * rstd * w[c] + b[c];
        orow[c] = xr[c] + gamma[c] * ln;
    }
}

// ---------------------------------------------------------------------------
// Tiled SGEMM: C[M,N] = act(alpha * A[M,K] @ B[N,K]^T + bias)
// BM=128, BN=64, BK=16, 256 threads, 8x4 per thread
// ---------------------------------------------------------------------------
template <bool GELU, bool HAS_BIAS>
__global__ __launch_bounds__(256) void gemm_kernel(
    const float* __restrict__ A, const float* __restrict__ B,
    const float* __restrict__ bias, float* __restrict__ C,
    int M, int N, int K, float alpha)
{
    constexpr int BM = 128, BN = 64, BK = 16, TM = 8, TN = 4;
    __shared__ float As[BK][BM + 4];
    __shared__ float Bs[BK][BN + 4];
    int tid = threadIdx.x;
    int tx = tid & 15, ty = tid >> 4;
    int m0 = blockIdx.y * BM;
    int n0 = blockIdx.x * BN;
    float acc[TM][TN] = {};

    for (int kt = 0; kt < K; kt += BK) {
        // A tile: 128x16 = 512 float4s, 2 per thread
#pragma unroll
        for (int j = 0; j < 2; j++) {
            int f = tid + j * 256;
            int row = f >> 2, c4 = f & 3;
            float4 v = *reinterpret_cast<const float4*>(
                &A[(size_t)(m0 + row) * K + kt + c4 * 4]);
            As[c4 * 4 + 0][row] = v.x; As[c4 * 4 + 1][row] = v.y;
            As[c4 * 4 + 2][row] = v.z; As[c4 * 4 + 3][row] = v.w;
        }
        // B tile: 64x16 = 256 float4s, 1 per thread
        {
            int f = tid;
            int row = f >> 2, c4 = f & 3;
            float4 v = *reinterpret_cast<const float4*>(
                &B[(size_t)(n0 + row) * K + kt + c4 * 4]);
            Bs[c4 * 4 + 0][row] = v.x; Bs[c4 * 4 + 1][row] = v.y;
            Bs[c4 * 4 + 2][row] = v.z; Bs[c4 * 4 + 3][row] = v.w;
        }
        __syncthreads();
#pragma unroll
        for (int k = 0; k < BK; k++) {
            float a[TM], bb[TN];
#pragma unroll
            for (int i = 0; i < TM; i++) a[i] = As[k][ty * TM + i];
#pragma unroll
            for (int j = 0; j < TN; j++) bb[j] = Bs[k][tx * TN + j];
#pragma unroll
            for (int i = 0; i < TM; i++)
#pragma unroll
                for (int j = 0; j < TN; j++)
                    acc[i][j] += a[i] * bb[j];
        }
        __syncthreads();
    }

#pragma unroll
    for (int i = 0; i < TM; i++) {
        int m = m0 + ty * TM + i;
        float4 v;
        float* vp = &v.x;
#pragma unroll
        for (int j = 0; j < TN; j++) {
            float c = acc[i][j] * alpha;
            if (HAS_BIAS) c += bias[n0 + tx * TN + j];
            if (GELU) c = 0.5f * c * (1.f + erff(c * 0.70710678118654752f));
            vp[j] = c;
        }
        *reinterpret_cast<float4*>(&C[(size_t)m * N + n0 + tx * TN]) = v;
    }
}

// ---------------------------------------------------------------------------
// Flash attention (one direction). One thread per query row (TQ=128/block).
// Q,K,V point at [rows, 256] buffers; head h uses columns [h*32, h*32+32).
// O written in the same (unheaded) layout.
// ---------------------------------------------------------------------------
#define TQ 128
#define TK 32
__global__ __launch_bounds__(128) void flash_kernel(
    const float* __restrict__ Q, const float* __restrict__ K,
    const float* __restrict__ V, float* __restrict__ O)
{
    __shared__ float4 Ks[TK][8];
    __shared__ float4 Vs[TK][8];

    int tid = threadIdx.x;
    int q = blockIdx.x * TQ + tid;
    int h = blockIdx.y;
    int b = blockIdx.z;
    size_t brow = (size_t)b * SEQ;

    const float* qrow = Q + (brow + q) * DIMC + h * HEAD_DIM;
    float4 qr[8];
#pragma unroll
    for (int i = 0; i < 8; i++) qr[i] = reinterpret_cast<const float4*>(qrow)[i];

    float4 o[8];
#pragma unroll
    for (int i = 0; i < 8; i++) o[i] = make_float4(0.f, 0.f, 0.f, 0.f);
    float mrun = -1e30f, lrun = 0.f;

    for (int kc = 0; kc < SEQ / TK; kc++) {
        // load K/V chunk: 32 rows x 8 float4 = 256 float4s, 2 per thread
#pragma unroll
        for (int j = 0; j < 2; j++) {
            int idx = tid + j * 128;
            int kr = idx >> 3, c = idx & 7;
            size_t grow = (brow + kc * TK + kr) * DIMC + h * HEAD_DIM;
            Ks[kr][c] = reinterpret_cast<const float4*>(K + grow)[c];
            Vs[kr][c] = reinterpret_cast<const float4*>(V + grow)[c];
        }
        __syncthreads();

        float s[TK];
        float cmax = -1e30f;
#pragma unroll 8
        for (int kk = 0; kk < TK; kk++) {
            float acc = 0.f;
#pragma unroll
            for (int d = 0; d < 8; d++) {
                float4 kv = Ks[kk][d];
                acc += qr[d].x * kv.x + qr[d].y * kv.y
                     + qr[d].z * kv.z + qr[d].w * kv.w;
            }
            s[kk] = acc;
            cmax = fmaxf(cmax, acc);
        }
        float newm = fmaxf(mrun, cmax);
        float corr = __expf(mrun - newm);
        lrun *= corr;
#pragma unroll
        for (int d = 0; d < 8; d++) {
            o[d].x *= corr; o[d].y *= corr; o[d].z *= corr; o[d].w *= corr;
        }
#pragma unroll 8
        for (int kk = 0; kk < TK; kk++) {
            float p = __expf(s[kk] - newm);
            lrun += p;
#pragma unroll
            for (int d = 0; d < 8; d++) {
                float4 vv = Vs[kk][d];
                o[d].x += p * vv.x; o[d].y += p * vv.y;
                o[d].z += p * vv.z; o[d].w += p * vv.w;
            }
        }
        mrun = newm;
        __syncthreads();
    }

    float inv = 1.f / lrun;
    float* orow = O + (brow + q) * DIMC + h * HEAD_DIM;
#pragma unroll
    for (int i = 0; i < 8; i++) {
        float4 v = o[i];
        v.x *= inv; v.y *= inv; v.z *= inv; v.w *= inv;
        reinterpret_cast<float4*>(orow)[i] = v;
    }
}

// ---------------------------------------------------------------------------
// Concat: cat[row] = [ x(row) (original input), mm(row) ]
// One thread per output float4: TOTAL_ROWS * 128 float4s
// ---------------------------------------------------------------------------
__global__ __launch_bounds__(256) void concat_kernel(
    const float* __restrict__ x0, const float* __restrict__ x1,
    const float* __restrict__ m, float* __restrict__ cat)
{
    int idx = blockIdx.x * 256 + threadIdx.x;   // over 8192*128
    int row = idx >> 7, c = idx & 127;
    float4 v;
    if (c < 64) {
        const float* src = (row < ROWS_PER_STREAM)
            ? x0 + (size_t)row * DIMC
            : x1 + (size_t)(row - ROWS_PER_STREAM) * DIMC;
        v = reinterpret_cast<const float4*>(src)[c];
    } else {
        v = reinterpret_cast<const float4*>(m + (size_t)row * DIMC)[c - 64];
    }
    reinterpret_cast<float4*>(cat)[(size_t)row * 128 + c] = v;
}

// ---------------------------------------------------------------------------
// Launch
// ---------------------------------------------------------------------------
extern "C" void kernel_launch(void* const* d_in, const int* in_sizes, int n_in,
                              void* d_out, int out_size)
{
    const float* x0      = (const float*)d_in[0];
    const float* x1      = (const float*)d_in[1];
    const float* qk_w    = (const float*)d_in[2];
    const float* v_w     = (const float*)d_in[3];
    const float* merge_w = (const float*)d_in[4];
    const float* ln1_w   = (const float*)d_in[5];
    const float* ln1_b   = (const float*)d_in[6];
    const float* ln2_w   = (const float*)d_in[7];
    const float* ln2_b   = (const float*)d_in[8];
    const float* fc1_w   = (const float*)d_in[9];
    const float* fc1_b   = (const float*)d_in[10];
    const float* fc2_w   = (const float*)d_in[11];
    const float* fc2_b   = (const float*)d_in[12];
    const float* gamma   = (const float*)d_in[13];
    float* out = (float*)d_out;

    float *nbuf, *qk, *v, *m, *mm, *cat, *h, *t;
    cudaGetSymbolAddress((void**)&nbuf, g_n);
    cudaGetSymbolAddress((void**)&qk,   g_qk);
    cudaGetSymbolAddress((void**)&v,    g_v);
    cudaGetSymbolAddress((void**)&m,    g_m);
    cudaGetSymbolAddress((void**)&mm,   g_mm);
    cudaGetSymbolAddress((void**)&cat,  g_cat);
    cudaGetSymbolAddress((void**)&h,    g_h);
    cudaGetSymbolAddress((void**)&t,    g_t);

    // 1. LayerNorm1 on both streams -> g_n (stacked)
    ln_kernel<<<ROWS_PER_STREAM / 8, 256>>>(x0, ln1_w, ln1_b, nbuf);
    ln_kernel<<<ROWS_PER_STREAM / 8, 256>>>(x1, ln1_w, ln1_b, nbuf + STREAM_OFF);

    // 2. Projections (qk gets scale baked in, applied to both sides)
    dim3 gP(DIMC / 64, TOTAL_ROWS / 128);
    gemm_kernel<false, false><<<gP, 256>>>(nbuf, qk_w, nullptr, qk,
                                           TOTAL_ROWS, DIMC, DIMC, QK_SCALE);
    gemm_kernel<false, false><<<gP, 256>>>(nbuf, v_w, nullptr, v,
                                           TOTAL_ROWS, DIMC, DIMC, 1.f);

    // 3. Dual flash attention
    //    m0 = softmax(sim,-1) @ v1   -> Q=qk0, K=qk1, V=v1
    //    m1 = softmax(sim,-2)^T @ v0 -> Q=qk1, K=qk0, V=v0
    dim3 gF(SEQ / TQ, HEADS, BATCH);
    flash_kernel<<<gF, 128>>>(qk, qk + STREAM_OFF, v + STREAM_OFF, m);
    flash_kernel<<<gF, 128>>>(qk + STREAM_OFF, qk, v, m + STREAM_OFF);

    // 4. Merge projection
    gemm_kernel<false, false><<<gP, 256>>>(m, merge_w, nullptr, mm,
                                           TOTAL_ROWS, DIMC, DIMC, 1.f);

    // 5. Concat [x, m] -> g_cat
    concat_kernel<<<TOTAL_ROWS * 128 / 256, 256>>>(x0, x1, mm, cat);

    // 6. fc1 + exact GELU
    dim3 gF1(HIDDEN / 64, TOTAL_ROWS / 128);
    gemm_kernel<true, true><<<gF1, 256>>>(cat, fc1_w, fc1_b, h,
                                          TOTAL_ROWS, HIDDEN, 2 * DIMC, 1.f);

    // 7. fc2
    gemm_kernel<false, true><<<gP, 256>>>(h, fc2_w, fc2_b, t,
                                          TOTAL_ROWS, DIMC, HIDDEN, 1.f);

    // 8. Residual + gamma * LN2 -> output (y0 then y1)
    final_kernel<<<ROWS_PER_STREAM / 8, 256>>>(t, x0, ln2_w, ln2_b, gamma, out);
    final_kernel<<<ROWS_PER_STREAM / 8, 256>>>(t + STREAM_OFF, x1, ln2_w, ln2_b,
                                               gamma, out + STREAM_OFF);
}

// round 2
// speedup vs baseline: 3.2566x; 3.2566x over previous
#include <cuda_runtime.h>
#include <cuda_bf16.h>
#include <cstdint>

// ---------------------------------------------------------------------------
// Problem constants
// ---------------------------------------------------------------------------
#define DIMC      256
#define HEADS     8
#define HEAD_DIM  32
#define HIDDEN    1024
#define SEQ       2048
#define BATCH     2
#define ROWS_PER_STREAM (BATCH * SEQ)          // 4096
#define TOTAL_ROWS      (2 * ROWS_PER_STREAM)  // 8192
#define STREAM_OFF      (ROWS_PER_STREAM * DIMC)

#define QK_SCALE 0.42044820762685725f  // HEAD_DIM^-0.25

// ---------------------------------------------------------------------------
// Scratch
// ---------------------------------------------------------------------------
__device__ float g_n  [TOTAL_ROWS * DIMC];
__device__ float g_qk [TOTAL_ROWS * DIMC];
__device__ float g_v  [TOTAL_ROWS * DIMC];
__device__ float g_m  [TOTAL_ROWS * DIMC];
__device__ float g_mm [TOTAL_ROWS * DIMC];
__device__ float g_cat[TOTAL_ROWS * 2 * DIMC];
__device__ float g_h  [TOTAL_ROWS * HIDDEN];
__device__ float g_t  [TOTAL_ROWS * DIMC];

// ---------------------------------------------------------------------------
// tf32 helpers
// ---------------------------------------------------------------------------
__device__ __forceinline__ uint32_t f2tf(float f) {
    uint32_t u;
    asm("cvt.rna.tf32.f32 %0, %1;" : "=r"(u) : "f"(f));
    return u;
}

__device__ __forceinline__ void mma_tf32(
    float& c0, float& c1, float& c2, float& c3,
    uint32_t a0, uint32_t a1, uint32_t a2, uint32_t a3,
    uint32_t b0, uint32_t b1)
{
    asm volatile(
        "mma.sync.aligned.m16n8k8.row.col.f32.tf32.tf32.f32 "
        "{%0,%1,%2,%3},{%4,%5,%6,%7},{%8,%9},{%0,%1,%2,%3};"
        : "+f"(c0), "+f"(c1), "+f"(c2), "+f"(c3)
        : "r"(a0), "r"(a1), "r"(a2), "r"(a3), "r"(b0), "r"(b1));
}

// ---------------------------------------------------------------------------
// LayerNorm: one warp per row
// ---------------------------------------------------------------------------
__global__ __launch_bounds__(256) void ln_kernel(
    const float* __restrict__ x, const float* __restrict__ w,
    const float* __restrict__ b, float* __restrict__ out)
{
    int warp = threadIdx.x >> 5, lane = threadIdx.x & 31;
    int row = blockIdx.x * 8 + warp;
    const float* xr = x + (size_t)row * DIMC;
    float v[8];
    float sum = 0.f;
#pragma unroll
    for (int i = 0; i < 8; i++) { v[i] = xr[lane + i * 32]; sum += v[i]; }
#pragma unroll
    for (int o = 16; o; o >>= 1) sum += __shfl_xor_sync(0xffffffffu, sum, o);
    float mean = sum * (1.f / 256.f);
    float vs = 0.f;
#pragma unroll
    for (int i = 0; i < 8; i++) { float d = v[i] - mean; vs += d * d; }
#pragma unroll
    for (int o = 16; o; o >>= 1) vs += __shfl_xor_sync(0xffffffffu, vs, o);
    float rstd = rsqrtf(vs * (1.f / 256.f) + 1e-5f);
    float* orow = out + (size_t)row * DIMC;
#pragma unroll
    for (int i = 0; i < 8; i++) {
        int c = lane + i * 32;
        orow[c] = (v[i] - mean) * rstd * w[c] + b[c];
    }
}

// ---------------------------------------------------------------------------
// Final: out = x + gamma * LayerNorm(t)
// ---------------------------------------------------------------------------
__global__ __launch_bounds__(256) void final_kernel(
    const float* __restrict__ t, const float* __restrict__ x,
    const float* __restrict__ w, const float* __restrict__ b,
    const float* __restrict__ gamma, float* __restrict__ out)
{
    int warp = threadIdx.x >> 5, lane = threadIdx.x & 31;
    int row = blockIdx.x * 8 + warp;
    const float* tr = t + (size_t)row * DIMC;
    const float* xr = x + (size_t)row * DIMC;
    float v[8];
    float sum = 0.f;
#pragma unroll
    for (int i = 0; i < 8; i++) { v[i] = tr[lane + i * 32]; sum += v[i]; }
#pragma unroll
    for (int o = 16; o; o >>= 1) sum += __shfl_xor_sync(0xffffffffu, sum, o);
    float mean = sum * (1.f / 256.f);
    float vs = 0.f;
#pragma unroll
    for (int i = 0; i < 8; i++) { float d = v[i] - mean; vs += d * d; }
#pragma unroll
    for (int o = 16; o; o >>= 1) vs += __shfl_xor_sync(0xffffffffu, vs, o);
    float rstd = rsqrtf(vs * (1.f / 256.f) + 1e-5f);
    float* orow = out + (size_t)row * DIMC;
#pragma unroll
    for (int i = 0; i < 8; i++) {
        int c = lane + i * 32;
        float ln = (v[i] - mean) * rstd * w[c] + b[c];
        orow[c] = xr[c] + gamma[c] * ln;
    }
}

// ---------------------------------------------------------------------------
// tf32 tensor-core GEMM: C[M,N] = act(alpha * A[M,K] @ B[N,K]^T + bias)
// BM=BN=128, BK=32, 256 threads (8 warps, 2x4), warp tile 64x32 (4x4 mma)
// ---------------------------------------------------------------------------
template <bool GELU, bool HAS_BIAS>
__global__ __launch_bounds__(256) void gemm_tc(
    const float* __restrict__ A, const float* __restrict__ B,
    const float* __restrict__ bias, float* __restrict__ C,
    int M, int N, int K, float alpha)
{
    constexpr int BM = 128, BN = 128, BK = 32;
    __shared__ uint32_t As[BM][BK + 4];   // stride 36: conflict-free frags
    __shared__ uint32_t Bs[BN][BK + 4];

    int tid = threadIdx.x;
    int wid = tid >> 5, lane = tid & 31;
    int grp = lane >> 2, tig = lane & 3;
    int warp_m = wid >> 2;   // 0..1
    int warp_n = wid & 3;    // 0..3
    int m0 = blockIdx.y * BM;
    int n0 = blockIdx.x * BN;

    float acc[4][4][4] = {};

    for (int kt = 0; kt < K; kt += BK) {
#pragma unroll
        for (int j = 0; j < 4; j++) {
            int idx = tid + j * 256;
            int r = idx >> 3, c4 = idx & 7;
            float4 v = *reinterpret_cast<const float4*>(
                &A[(size_t)(m0 + r) * K + kt + c4 * 4]);
            uint4 u = make_uint4(f2tf(v.x), f2tf(v.y), f2tf(v.z), f2tf(v.w));
            *reinterpret_cast<uint4*>(&As[r][c4 * 4]) = u;
        }
#pragma unroll
        for (int j = 0; j < 4; j++) {
            int idx = tid + j * 256;
            int r = idx >> 3, c4 = idx & 7;
            float4 v = *reinterpret_cast<const float4*>(
                &B[(size_t)(n0 + r) * K + kt + c4 * 4]);
            uint4 u = make_uint4(f2tf(v.x), f2tf(v.y), f2tf(v.z), f2tf(v.w));
            *reinterpret_cast<uint4*>(&Bs[r][c4 * 4]) = u;
        }
        __syncthreads();

#pragma unroll
        for (int ks = 0; ks < 4; ks++) {
            int k0 = ks * 8;
            uint32_t af[4][4], bf[4][2];
#pragma unroll
            for (int mt = 0; mt < 4; mt++) {
                int mr = warp_m * 64 + mt * 16;
                af[mt][0] = As[mr + grp    ][k0 + tig    ];
                af[mt][1] = As[mr + grp + 8][k0 + tig    ];
                af[mt][2] = As[mr + grp    ][k0 + tig + 4];
                af[mt][3] = As[mr + grp + 8][k0 + tig + 4];
            }
#pragma unroll
            for (int nt = 0; nt < 4; nt++) {
                int nr = warp_n * 32 + nt * 8;
                bf[nt][0] = Bs[nr + grp][k0 + tig    ];
                bf[nt][1] = Bs[nr + grp][k0 + tig + 4];
            }
#pragma unroll
            for (int mt = 0; mt < 4; mt++)
#pragma unroll
                for (int nt = 0; nt < 4; nt++)
                    mma_tf32(acc[mt][nt][0], acc[mt][nt][1],
                             acc[mt][nt][2], acc[mt][nt][3],
                             af[mt][0], af[mt][1], af[mt][2], af[mt][3],
                             bf[nt][0], bf[nt][1]);
        }
        __syncthreads();
    }

#pragma unroll
    for (int mt = 0; mt < 4; mt++) {
        int mr = m0 + warp_m * 64 + mt * 16;
#pragma unroll
        for (int nt = 0; nt < 4; nt++) {
            int nc = n0 + warp_n * 32 + nt * 8 + 2 * tig;
            float b0 = 0.f, b1 = 0.f;
            if (HAS_BIAS) { b0 = bias[nc]; b1 = bias[nc + 1]; }
            float v0 = acc[mt][nt][0] * alpha + b0;
            float v1 = acc[mt][nt][1] * alpha + b1;
            float v2 = acc[mt][nt][2] * alpha + b0;
            float v3 = acc[mt][nt][3] * alpha + b1;
            if (GELU) {
                v0 = 0.5f * v0 * (1.f + erff(v0 * 0.70710678118654752f));
                v1 = 0.5f * v1 * (1.f + erff(v1 * 0.70710678118654752f));
                v2 = 0.5f * v2 * (1.f + erff(v2 * 0.70710678118654752f));
                v3 = 0.5f * v3 * (1.f + erff(v3 * 0.70710678118654752f));
            }
            *reinterpret_cast<float2*>(&C[(size_t)(mr + grp) * N + nc]) =
                make_float2(v0, v1);
            *reinterpret_cast<float2*>(&C[(size_t)(mr + grp + 8) * N + nc]) =
                make_float2(v2, v3);
        }
    }
}

// ---------------------------------------------------------------------------
// tf32 tensor-core flash attention.
// Block: 128 threads (4 warps), 64 queries (16 per warp), key chunks of 64.
// Q,K,V are [rows,256] buffers; head h -> cols [h*32, h*32+32).
// ---------------------------------------------------------------------------
__global__ __launch_bounds__(128) void flash_tc(
    const float* __restrict__ Q, const float* __restrict__ K,
    const float* __restrict__ V, float* __restrict__ O)
{
    __shared__ uint32_t Ks[64][36];        // [key][dh], stride 36
    __shared__ uint32_t Vs[64][40];        // [key][dh], stride 40
    __shared__ uint32_t Ps[4][16][68];     // per-warp P tile, stride 68

    int tid = threadIdx.x;
    int wid = tid >> 5, lane = tid & 31;
    int grp = lane >> 2, tig = lane & 3;
    int h = blockIdx.y, b = blockIdx.z;
    size_t brow = (size_t)b * SEQ;
    int q0 = blockIdx.x * 64 + wid * 16;

    // Q fragments (register resident): qa[ks][4], ks covers dh in steps of 8
    uint32_t qa[4][4];
    const float* Qb = Q + (brow + q0) * DIMC + h * HEAD_DIM;
#pragma unroll
    for (int ks = 0; ks < 4; ks++) {
        qa[ks][0] = f2tf(Qb[(size_t)(grp    ) * DIMC + ks * 8 + tig    ]);
        qa[ks][1] = f2tf(Qb[(size_t)(grp + 8) * DIMC + ks * 8 + tig    ]);
        qa[ks][2] = f2tf(Qb[(size_t)(grp    ) * DIMC + ks * 8 + tig + 4]);
        qa[ks][3] = f2tf(Qb[(size_t)(grp + 8) * DIMC + ks * 8 + tig + 4]);
    }

    float oacc[4][4] = {};
    float mr0 = -1e30f, mr1 = -1e30f, l0 = 0.f, l1 = 0.f;

    for (int kc = 0; kc < SEQ / 64; kc++) {
        // load K,V chunk (64 x 32 each): 512 float4 each, 4 per thread
#pragma unroll
        for (int j = 0; j < 4; j++) {
            int idx = tid + j * 128;
            int r = idx >> 3, c4 = idx & 7;
            size_t g = (brow + (size_t)kc * 64 + r) * DIMC + h * HEAD_DIM + c4 * 4;
            float4 kv = *reinterpret_cast<const float4*>(&K[g]);
            *reinterpret_cast<uint4*>(&Ks[r][c4 * 4]) =
                make_uint4(f2tf(kv.x), f2tf(kv.y), f2tf(kv.z), f2tf(kv.w));
            float4 vv = *reinterpret_cast<const float4*>(&V[g]);
            *reinterpret_cast<uint4*>(&Vs[r][c4 * 4]) =
                make_uint4(f2tf(vv.x), f2tf(vv.y), f2tf(vv.z), f2tf(vv.w));
        }
        __syncthreads();

        // S = Q @ K^T : 8 n-tiles of 8 keys
        float s[8][4] = {};
#pragma unroll
        for (int ks = 0; ks < 4; ks++) {
            int k0 = ks * 8;
#pragma unroll
            for (int nt = 0; nt < 8; nt++) {
                uint32_t b0 = Ks[nt * 8 + grp][k0 + tig    ];
                uint32_t b1 = Ks[nt * 8 + grp][k0 + tig + 4];
                mma_tf32(s[nt][0], s[nt][1], s[nt][2], s[nt][3],
                         qa[ks][0], qa[ks][1], qa[ks][2], qa[ks][3], b0, b1);
            }
        }

        // online softmax: rows r0=grp, r1=grp+8 (warp-local)
        float cm0 = -1e30f, cm1 = -1e30f;
#pragma unroll
        for (int nt = 0; nt < 8; nt++) {
            cm0 = fmaxf(cm0, fmaxf(s[nt][0], s[nt][1]));
            cm1 = fmaxf(cm1, fmaxf(s[nt][2], s[nt][3]));
        }
        cm0 = fmaxf(cm0, __shfl_xor_sync(0xffffffffu, cm0, 1));
        cm0 = fmaxf(cm0, __shfl_xor_sync(0xffffffffu, cm0, 2));
        cm1 = fmaxf(cm1, __shfl_xor_sync(0xffffffffu, cm1, 1));
        cm1 = fmaxf(cm1, __shfl_xor_sync(0xffffffffu, cm1, 2));
        float nm0 = fmaxf(mr0, cm0), nm1 = fmaxf(mr1, cm1);
        float corr0 = __expf(mr0 - nm0), corr1 = __expf(mr1 - nm1);

        float sum0 = 0.f, sum1 = 0.f;
#pragma unroll
        for (int nt = 0; nt < 8; nt++) {
            float p0 = __expf(s[nt][0] - nm0);
            float p1 = __expf(s[nt][1] - nm0);
            float p2 = __expf(s[nt][2] - nm1);
            float p3 = __expf(s[nt][3] - nm1);
            sum0 += p0 + p1;
            sum1 += p2 + p3;
            *reinterpret_cast<uint2*>(&Ps[wid][grp    ][nt * 8 + 2 * tig]) =
                make_uint2(f2tf(p0), f2tf(p1));
            *reinterpret_cast<uint2*>(&Ps[wid][grp + 8][nt * 8 + 2 * tig]) =
                make_uint2(f2tf(p2), f2tf(p3));
        }
        sum0 += __shfl_xor_sync(0xffffffffu, sum0, 1);
        sum0 += __shfl_xor_sync(0xffffffffu, sum0, 2);
        sum1 += __shfl_xor_sync(0xffffffffu, sum1, 1);
        sum1 += __shfl_xor_sync(0xffffffffu, sum1, 2);
        l0 = l0 * corr0 + sum0;
        l1 = l1 * corr1 + sum1;
        mr0 = nm0; mr1 = nm1;

#pragma unroll
        for (int nt = 0; nt < 4; nt++) {
            oacc[nt][0] *= corr0; oacc[nt][1] *= corr0;
            oacc[nt][2] *= corr1; oacc[nt][3] *= corr1;
        }
        __syncwarp();

        // O += P @ V : 8 k-steps over 64 keys, 4 n-tiles over 32 dh
#pragma unroll
        for (int ks = 0; ks < 8; ks++) {
            int k0 = ks * 8;
            uint32_t a0 = Ps[wid][grp    ][k0 + tig    ];
            uint32_t a1 = Ps[wid][grp + 8][k0 + tig    ];
            uint32_t a2 = Ps[wid][grp    ][k0 + tig + 4];
            uint32_t a3 = Ps[wid][grp + 8][k0 + tig + 4];
#pragma unroll
            for (int nt = 0; nt < 4; nt++) {
                uint32_t b0 = Vs[k0 + tig    ][nt * 8 + grp];
                uint32_t b1 = Vs[k0 + tig + 4][nt * 8 + grp];
                mma_tf32(oacc[nt][0], oacc[nt][1], oacc[nt][2], oacc[nt][3],
                         a0, a1, a2, a3, b0, b1);
            }
        }
        __syncthreads();
    }

    float inv0 = 1.f / l0, inv1 = 1.f / l1;
    float* Ob = O + (brow + q0) * DIMC + h * HEAD_DIM;
#pragma unroll
    for (int nt = 0; nt < 4; nt++) {
        int c = nt * 8 + 2 * tig;
        *reinterpret_cast<float2*>(&Ob[(size_t)(grp    ) * DIMC + c]) =
            make_float2(oacc[nt][0] * inv0, oacc[nt][1] * inv0);
        *reinterpret_cast<float2*>(&Ob[(size_t)(grp + 8) * DIMC + c]) =
            make_float2(oacc[nt][2] * inv1, oacc[nt][3] * inv1);
    }
}

// ---------------------------------------------------------------------------
// Concat: cat[row] = [ x(row), mm(row) ]
// ---------------------------------------------------------------------------
__global__ __launch_bounds__(256) void concat_kernel(
    const float* __restrict__ x0, const float* __restrict__ x1,
    const float* __restrict__ m, float* __restrict__ cat)
{
    int idx = blockIdx.x * 256 + threadIdx.x;
    int row = idx >> 7, c = idx & 127;
    float4 v;
    if (c < 64) {
        const float* src = (row < ROWS_PER_STREAM)
            ? x0 + (size_t)row * DIMC
            : x1 + (size_t)(row - ROWS_PER_STREAM) * DIMC;
        v = reinterpret_cast<const float4*>(src)[c];
    } else {
        v = reinterpret_cast<const float4*>(m + (size_t)row * DIMC)[c - 64];
    }
    reinterpret_cast<float4*>(cat)[(size_t)row * 128 + c] = v;
}

// ---------------------------------------------------------------------------
// Launch
// ---------------------------------------------------------------------------
extern "C" void kernel_launch(void* const* d_in, const int* in_sizes, int n_in,
                              void* d_out, int out_size)
{
    const float* x0      = (const float*)d_in[0];
    const float* x1      = (const float*)d_in[1];
    const float* qk_w    = (const float*)d_in[2];
    const float* v_w     = (const float*)d_in[3];
    const float* merge_w = (const float*)d_in[4];
    const float* ln1_w   = (const float*)d_in[5];
    const float* ln1_b   = (const float*)d_in[6];
    const float* ln2_w   = (const float*)d_in[7];
    const float* ln2_b   = (const float*)d_in[8];
    const float* fc1_w   = (const float*)d_in[9];
    const float* fc1_b   = (const float*)d_in[10];
    const float* fc2_w   = (const float*)d_in[11];
    const float* fc2_b   = (const float*)d_in[12];
    const float* gamma   = (const float*)d_in[13];
    float* out = (float*)d_out;

    float *nbuf, *qk, *v, *m, *mm, *cat, *h, *t;
    cudaGetSymbolAddress((void**)&nbuf, g_n);
    cudaGetSymbolAddress((void**)&qk,   g_qk);
    cudaGetSymbolAddress((void**)&v,    g_v);
    cudaGetSymbolAddress((void**)&m,    g_m);
    cudaGetSymbolAddress((void**)&mm,   g_mm);
    cudaGetSymbolAddress((void**)&cat,  g_cat);
    cudaGetSymbolAddress((void**)&h,    g_h);
    cudaGetSymbolAddress((void**)&t,    g_t);

    // 1. LayerNorm1
    ln_kernel<<<ROWS_PER_STREAM / 8, 256>>>(x0, ln1_w, ln1_b, nbuf);
    ln_kernel<<<ROWS_PER_STREAM / 8, 256>>>(x1, ln1_w, ln1_b, nbuf + STREAM_OFF);

    // 2. Projections (tf32 tensor cores); qk gets scale baked in
    dim3 gP(DIMC / 128, TOTAL_ROWS / 128);
    gemm_tc<false, false><<<gP, 256>>>(nbuf, qk_w, nullptr, qk,
                                       TOTAL_ROWS, DIMC, DIMC, QK_SCALE);
    gemm_tc<false, false><<<gP, 256>>>(nbuf, v_w, nullptr, v,
                                       TOTAL_ROWS, DIMC, DIMC, 1.f);

    // 3. Dual flash attention (tensor cores)
    dim3 gF(SEQ / 64, HEADS, BATCH);
    flash_tc<<<gF, 128>>>(qk, qk + STREAM_OFF, v + STREAM_OFF, m);
    flash_tc<<<gF, 128>>>(qk + STREAM_OFF, qk, v, m + STREAM_OFF);

    // 4. Merge projection
    gemm_tc<false, false><<<gP, 256>>>(m, merge_w, nullptr, mm,
                                       TOTAL_ROWS, DIMC, DIMC, 1.f);

    // 5. Concat [x, m]
    concat_kernel<<<TOTAL_ROWS * 128 / 256, 256>>>(x0, x1, mm, cat);

    // 6. fc1 + exact GELU
    dim3 gF1(HIDDEN / 128, TOTAL_ROWS / 128);
    gemm_tc<true, true><<<gF1, 256>>>(cat, fc1_w, fc1_b, h,
                                      TOTAL_ROWS, HIDDEN, 2 * DIMC, 1.f);

    // 7. fc2
    gemm_tc<false, true><<<gP, 256>>>(h, fc2_w, fc2_b, t,
                                      TOTAL_ROWS, DIMC, HIDDEN, 1.f);

    // 8. Residual + gamma * LN2
    final_kernel<<<ROWS_PER_STREAM / 8, 256>>>(t, x0, ln2_w, ln2_b, gamma, out);
    final_kernel<<<ROWS_PER_STREAM / 8, 256>>>(t + STREAM_OFF, x1, ln2_w, ln2_b,
                                               gamma, out + STREAM_OFF);
}

// round 3
// speedup vs baseline: 3.7990x; 1.1666x over previous
#include <cuda_runtime.h>
#include <cuda_bf16.h>
#include <cstdint>

// ---------------------------------------------------------------------------
// Problem constants
// ---------------------------------------------------------------------------
#define DIMC      256
#define HEADS     8
#define HEAD_DIM  32
#define HIDDEN    1024
#define SEQ       2048
#define BATCH     2
#define RPS       (BATCH * SEQ)          // 4096 rows per stream
#define TOTAL_ROWS (2 * RPS)             // 8192
#define STREAM_OFF (RPS * DIMC)

#define QK_SCALE 0.42044820762685725f    // HEAD_DIM^-0.25

// ---------------------------------------------------------------------------
// Scratch
// ---------------------------------------------------------------------------
__device__ float g_n  [TOTAL_ROWS * DIMC];
__device__ float g_qk [TOTAL_ROWS * DIMC];
__device__ float g_v  [TOTAL_ROWS * DIMC];
__device__ float g_m  [TOTAL_ROWS * DIMC];
__device__ float g_mm [TOTAL_ROWS * DIMC];
__device__ float g_h  [TOTAL_ROWS * HIDDEN];
__device__ float g_t  [TOTAL_ROWS * DIMC];

// ---------------------------------------------------------------------------
// PTX helpers
// ---------------------------------------------------------------------------
__device__ __forceinline__ uint32_t f2tf(float f) {
    uint32_t u;
    asm("cvt.rna.tf32.f32 %0, %1;" : "=r"(u) : "f"(f));
    return u;
}

__device__ __forceinline__ void mma_tf32(
    float& c0, float& c1, float& c2, float& c3,
    uint32_t a0, uint32_t a1, uint32_t a2, uint32_t a3,
    uint32_t b0, uint32_t b1)
{
    asm volatile(
        "mma.sync.aligned.m16n8k8.row.col.f32.tf32.tf32.f32 "
        "{%0,%1,%2,%3},{%4,%5,%6,%7},{%8,%9},{%0,%1,%2,%3};"
        : "+f"(c0), "+f"(c1), "+f"(c2), "+f"(c3)
        : "r"(a0), "r"(a1), "r"(a2), "r"(a3), "r"(b0), "r"(b1));
}

__device__ __forceinline__ uint32_t smem_u32(const void* p) {
    return (uint32_t)__cvta_generic_to_shared(p);
}
__device__ __forceinline__ void cp_async16(uint32_t dst, const void* src) {
    asm volatile("cp.async.cg.shared.global [%0], [%1], 16;"
                 :: "r"(dst), "l"(src));
}
__device__ __forceinline__ void cp_commit() {
    asm volatile("cp.async.commit_group;");
}
template <int N>
__device__ __forceinline__ void cp_wait() {
    asm volatile("cp.async.wait_group %0;" :: "n"(N));
}

// ---------------------------------------------------------------------------
// LayerNorm over both streams: one warp per row
// ---------------------------------------------------------------------------
__global__ __launch_bounds__(256) void ln_kernel(
    const float* __restrict__ x0, const float* __restrict__ x1,
    const float* __restrict__ w, const float* __restrict__ b,
    float* __restrict__ out)
{
    int warp = threadIdx.x >> 5, lane = threadIdx.x & 31;
    int row = blockIdx.x * 8 + warp;
    const float* xr = (row < RPS) ? x0 + (size_t)row * DIMC
                                  : x1 + (size_t)(row - RPS) * DIMC;
    float v[8];
    float sum = 0.f;
#pragma unroll
    for (int i = 0; i < 8; i++) { v[i] = xr[lane + i * 32]; sum += v[i]; }
#pragma unroll
    for (int o = 16; o; o >>= 1) sum += __shfl_xor_sync(0xffffffffu, sum, o);
    float mean = sum * (1.f / 256.f);
    float vs = 0.f;
#pragma unroll
    for (int i = 0; i < 8; i++) { float d = v[i] - mean; vs += d * d; }
#pragma unroll
    for (int o = 16; o; o >>= 1) vs += __shfl_xor_sync(0xffffffffu, vs, o);
    float rstd = rsqrtf(vs * (1.f / 256.f) + 1e-5f);
    float* orow = out + (size_t)row * DIMC;
#pragma unroll
    for (int i = 0; i < 8; i++) {
        int c = lane + i * 32;
        orow[c] = (v[i] - mean) * rstd * w[c] + b[c];
    }
}

// ---------------------------------------------------------------------------
// Final: out = x + gamma * LayerNorm(t), both streams
// ---------------------------------------------------------------------------
__global__ __launch_bounds__(256) void final_kernel(
    const float* __restrict__ t,
    const float* __restrict__ x0, const float* __restrict__ x1,
    const float* __restrict__ w, const float* __restrict__ b,
    const float* __restrict__ gamma, float* __restrict__ out)
{
    int warp = threadIdx.x >> 5, lane = threadIdx.x & 31;
    int row = blockIdx.x * 8 + warp;
    const float* tr = t + (size_t)row * DIMC;
    const float* xr = (row < RPS) ? x0 + (size_t)row * DIMC
                                  : x1 + (size_t)(row - RPS) * DIMC;
    float v[8];
    float sum = 0.f;
#pragma unroll
    for (int i = 0; i < 8; i++) { v[i] = tr[lane + i * 32]; sum += v[i]; }
#pragma unroll
    for (int o = 16; o; o >>= 1) sum += __shfl_xor_sync(0xffffffffu, sum, o);
    float mean = sum * (1.f / 256.f);
    float vs = 0.f;
#pragma unroll
    for (int i = 0; i < 8; i++) { float d = v[i] - mean; vs += d * d; }
#pragma unroll
    for (int o = 16; o; o >>= 1) vs += __shfl_xor_sync(0xffffffffu, vs, o);
    float rstd = rsqrtf(vs * (1.f / 256.f) + 1e-5f);
    float* orow = out + (size_t)row * DIMC;
#pragma unroll
    for (int i = 0; i < 8; i++) {
        int c = lane + i * 32;
        float ln = (v[i] - mean) * rstd * w[c] + b[c];
        orow[c] = xr[c] + gamma[c] * ln;
    }
}

// ---------------------------------------------------------------------------
// cp.async double-buffered tf32 GEMM.
// C[M,Nout] = act(alpha * A[M,K] @ B[Nout,K]^T + bias)
// BM=BN=128, BK=32, 256 threads (8 warps 2x4), warp tile 64x32.
// DUAL: grid.x spans 2*Nout cols; first half -> B0/C0/alpha0, second -> B1/C1/alpha1
// CAT : A column kk<DIMC comes from x (A0/A1 per stream row), else from Am.
// Dynamic smem: 2 stages x (A 128x36 + B 128x36) floats = 73728 B.
// ---------------------------------------------------------------------------
#define GEMM_SMEM (2 * 2 * 128 * 36 * 4)

template <bool GELU, bool HAS_BIAS, bool DUAL, bool CAT>
__global__ __launch_bounds__(256) void gemm_tc(
    const float* __restrict__ A0, const float* __restrict__ A1,
    const float* __restrict__ Am,
    const float* __restrict__ B0, const float* __restrict__ B1,
    const float* __restrict__ bias,
    float* __restrict__ C0, float* __restrict__ C1,
    int Nout, int K, float alpha0, float alpha1)
{
    constexpr int BK = 32;
    extern __shared__ float dsm[];
    float* AsBase = dsm;               // [2][128][36]
    float* BsBase = dsm + 2 * 128 * 36;

    int tid = threadIdx.x;
    int wid = tid >> 5, lane = tid & 31;
    int grp = lane >> 2, tig = lane & 3;
    int warp_m = wid >> 2, warp_n = wid & 3;
    int m0 = blockIdx.y * 128;
    int n0 = blockIdx.x * 128;

    const float* Bp;
    float* Cp;
    float alpha;
    if (DUAL) {
        if (n0 < Nout) { Bp = B0 + (size_t)n0 * K; Cp = C0; alpha = alpha0; }
        else { n0 -= Nout; Bp = B1 + (size_t)n0 * K; Cp = C1; alpha = alpha1; }
    } else {
        Bp = B0 + (size_t)n0 * K; Cp = C0; alpha = alpha0;
    }

    float acc[4][4][4] = {};
    int KT = K / BK;

    // --- stage loader ---
    auto load_stage = [&](int ktb, int s) {
        float* Ad = AsBase + s * (128 * 36);
        float* Bd = BsBase + s * (128 * 36);
#pragma unroll
        for (int j = 0; j < 4; j++) {
            int idx = tid + j * 256;
            int r = idx >> 3, c4 = idx & 7;
            int kk = ktb + c4 * 4;
            const float* src;
            if (CAT) {
                int row = m0 + r;
                if (kk < DIMC) {
                    const float* x = (row < RPS) ? A0 + (size_t)row * DIMC
                                                 : A1 + (size_t)(row - RPS) * DIMC;
                    src = x + kk;
                } else {
                    src = Am + (size_t)row * DIMC + (kk - DIMC);
                }
            } else {
                src = A0 + (size_t)(m0 + r) * K + kk;
            }
            cp_async16(smem_u32(&Ad[r * 36 + c4 * 4]), src);
        }
#pragma unroll
        for (int j = 0; j < 4; j++) {
            int idx = tid + j * 256;
            int r = idx >> 3, c4 = idx & 7;
            cp_async16(smem_u32(&Bd[r * 36 + c4 * 4]),
                       Bp + (size_t)r * K + ktb + c4 * 4);
        }
        cp_commit();
    };

    load_stage(0, 0);

    for (int kt = 0; kt < KT; kt++) {
        int s = kt & 1;
        if (kt + 1 < KT) { load_stage((kt + 1) * BK, s ^ 1); cp_wait<1>(); }
        else             { cp_wait<0>(); }
        __syncthreads();

        const float* Ad = AsBase + s * (128 * 36);
        const float* Bd = BsBase + s * (128 * 36);
#pragma unroll
        for (int ks = 0; ks < 4; ks++) {
            int k0 = ks * 8;
            uint32_t af[4][4], bf[4][2];
#pragma unroll
            for (int mt = 0; mt < 4; mt++) {
                int mr = warp_m * 64 + mt * 16;
                af[mt][0] = f2tf(Ad[(mr + grp    ) * 36 + k0 + tig    ]);
                af[mt][1] = f2tf(Ad[(mr + grp + 8) * 36 + k0 + tig    ]);
                af[mt][2] = f2tf(Ad[(mr + grp    ) * 36 + k0 + tig + 4]);
                af[mt][3] = f2tf(Ad[(mr + grp + 8) * 36 + k0 + tig + 4]);
            }
#pragma unroll
            for (int nt = 0; nt < 4; nt++) {
                int nr = warp_n * 32 + nt * 8;
                bf[nt][0] = f2tf(Bd[(nr + grp) * 36 + k0 + tig    ]);
                bf[nt][1] = f2tf(Bd[(nr + grp) * 36 + k0 + tig + 4]);
            }
#pragma unroll
            for (int mt = 0; mt < 4; mt++)
#pragma unroll
                for (int nt = 0; nt < 4; nt++)
                    mma_tf32(acc[mt][nt][0], acc[mt][nt][1],
                             acc[mt][nt][2], acc[mt][nt][3],
                             af[mt][0], af[mt][1], af[mt][2], af[mt][3],
                             bf[nt][0], bf[nt][1]);
        }
        __syncthreads();
    }

#pragma unroll
    for (int mt = 0; mt < 4; mt++) {
        int mr = m0 + warp_m * 64 + mt * 16;
#pragma unroll
        for (int nt = 0; nt < 4; nt++) {
            int nc = n0 + warp_n * 32 + nt * 8 + 2 * tig;
            float b0 = 0.f, b1 = 0.f;
            if (HAS_BIAS) { b0 = bias[nc]; b1 = bias[nc + 1]; }
            float v0 = acc[mt][nt][0] * alpha + b0;
            float v1 = acc[mt][nt][1] * alpha + b1;
            float v2 = acc[mt][nt][2] * alpha + b0;
            float v3 = acc[mt][nt][3] * alpha + b1;
            if (GELU) {
                v0 = 0.5f * v0 * (1.f + erff(v0 * 0.70710678118654752f));
                v1 = 0.5f * v1 * (1.f + erff(v1 * 0.70710678118654752f));
                v2 = 0.5f * v2 * (1.f + erff(v2 * 0.70710678118654752f));
                v3 = 0.5f * v3 * (1.f + erff(v3 * 0.70710678118654752f));
            }
            *reinterpret_cast<float2*>(&Cp[(size_t)(mr + grp) * Nout + nc]) =
                make_float2(v0, v1);
            *reinterpret_cast<float2*>(&Cp[(size_t)(mr + grp + 8) * Nout + nc]) =
                make_float2(v2, v3);
        }
    }
}

// ---------------------------------------------------------------------------
// tf32 flash attention, both directions in one launch.
// Block: 128 threads (4 warps), 64 queries, key chunks of 64, cp.async 2-stage.
// grid: (SEQ/64, HEADS, 2*BATCH); z: b = z&1, dir = z>>1
// Dynamic smem: K 2x64x36 + V 2x64x40 + P 4x16x68 floats = 56320 B.
// ---------------------------------------------------------------------------
#define FLASH_SMEM ((2*64*36 + 2*64*40 + 4*16*68) * 4)

__global__ __launch_bounds__(128) void flash_tc(
    const float* __restrict__ qkb, const float* __restrict__ vb,
    float* __restrict__ mb)
{
    extern __shared__ float dsm[];
    float* KsB = dsm;                      // [2][64][36]
    float* VsB = dsm + 2 * 64 * 36;        // [2][64][40]
    float* PsB = VsB + 2 * 64 * 40;        // [4][16][68]

    int tid = threadIdx.x;
    int wid = tid >> 5, lane = tid & 31;
    int grp = lane >> 2, tig = lane & 3;
    int h = blockIdx.y;
    int z = blockIdx.z;
    int b = z & 1, dir = z >> 1;

    const float* Q  = dir ? qkb + STREAM_OFF : qkb;
    const float* Kp = dir ? qkb : qkb + STREAM_OFF;
    const float* Vp = dir ? vb  : vb  + STREAM_OFF;
    float*       O  = dir ? mb + STREAM_OFF : mb;

    size_t brow = (size_t)b * SEQ;
    int q0 = blockIdx.x * 64 + wid * 16;
    float* Ps = PsB + wid * (16 * 68);

    // register-resident Q fragments
    uint32_t qa[4][4];
    const float* Qb = Q + (brow + q0) * DIMC + h * HEAD_DIM;
#pragma unroll
    for (int ks = 0; ks < 4; ks++) {
        qa[ks][0] = f2tf(Qb[(size_t)(grp    ) * DIMC + ks * 8 + tig    ]);
        qa[ks][1] = f2tf(Qb[(size_t)(grp + 8) * DIMC + ks * 8 + tig    ]);
        qa[ks][2] = f2tf(Qb[(size_t)(grp    ) * DIMC + ks * 8 + tig + 4]);
        qa[ks][3] = f2tf(Qb[(size_t)(grp + 8) * DIMC + ks * 8 + tig + 4]);
    }

    auto load_chunk = [&](int kc, int s) {
        float* Kd = KsB + s * (64 * 36);
        float* Vd = VsB + s * (64 * 40);
#pragma unroll
        for (int j = 0; j < 4; j++) {
            int idx = tid + j * 128;
            int r = idx >> 3, c4 = idx & 7;
            size_t g = (brow + (size_t)kc * 64 + r) * DIMC + h * HEAD_DIM + c4 * 4;
            cp_async16(smem_u32(&Kd[r * 36 + c4 * 4]), Kp + g);
            cp_async16(smem_u32(&Vd[r * 40 + c4 * 4]), Vp + g);
        }
        cp_commit();
    };

    float oacc[4][4] = {};
    float mr0 = -1e30f, mr1 = -1e30f, l0 = 0.f, l1 = 0.f;
    constexpr int NC = SEQ / 64;

    load_chunk(0, 0);

    for (int kc = 0; kc < NC; kc++) {
        int s = kc & 1;
        if (kc + 1 < NC) { load_chunk(kc + 1, s ^ 1); cp_wait<1>(); }
        else             { cp_wait<0>(); }
        __syncthreads();

        const float* Kd = KsB + s * (64 * 36);
        const float* Vd = VsB + s * (64 * 40);

        // S = Q @ K^T
        float sf[8][4] = {};
#pragma unroll
        for (int ks = 0; ks < 4; ks++) {
            int k0 = ks * 8;
#pragma unroll
            for (int nt = 0; nt < 8; nt++) {
                uint32_t b0 = f2tf(Kd[(nt * 8 + grp) * 36 + k0 + tig    ]);
                uint32_t b1 = f2tf(Kd[(nt * 8 + grp) * 36 + k0 + tig + 4]);
                mma_tf32(sf[nt][0], sf[nt][1], sf[nt][2], sf[nt][3],
                         qa[ks][0], qa[ks][1], qa[ks][2], qa[ks][3], b0, b1);
            }
        }

        // online softmax (rows grp, grp+8; reduce over tig quad)
        float cm0 = -1e30f, cm1 = -1e30f;
#pragma unroll
        for (int nt = 0; nt < 8; nt++) {
            cm0 = fmaxf(cm0, fmaxf(sf[nt][0], sf[nt][1]));
            cm1 = fmaxf(cm1, fmaxf(sf[nt][2], sf[nt][3]));
        }
        cm0 = fmaxf(cm0, __shfl_xor_sync(0xffffffffu, cm0, 1));
        cm0 = fmaxf(cm0, __shfl_xor_sync(0xffffffffu, cm0, 2));
        cm1 = fmaxf(cm1, __shfl_xor_sync(0xffffffffu, cm1, 1));
        cm1 = fmaxf(cm1, __shfl_xor_sync(0xffffffffu, cm1, 2));
        float nm0 = fmaxf(mr0, cm0), nm1 = fmaxf(mr1, cm1);
        float corr0 = __expf(mr0 - nm0), corr1 = __expf(mr1 - nm1);

        float sum0 = 0.f, sum1 = 0.f;
#pragma unroll
        for (int nt = 0; nt < 8; nt++) {
            float p0 = __expf(sf[nt][0] - nm0);
            float p1 = __expf(sf[nt][1] - nm0);
            float p2 = __expf(sf[nt][2] - nm1);
            float p3 = __expf(sf[nt][3] - nm1);
            sum0 += p0 + p1;
            sum1 += p2 + p3;
            *reinterpret_cast<uint2*>(&Ps[grp * 68 + nt * 8 + 2 * tig]) =
                make_uint2(f2tf(p0), f2tf(p1));
            *reinterpret_cast<uint2*>(&Ps[(grp + 8) * 68 + nt * 8 + 2 * tig]) =
                make_uint2(f2tf(p2), f2tf(p3));
        }
        sum0 += __shfl_xor_sync(0xffffffffu, sum0, 1);
        sum0 += __shfl_xor_sync(0xffffffffu, sum0, 2);
        sum1 += __shfl_xor_sync(0xffffffffu, sum1, 1);
        sum1 += __shfl_xor_sync(0xffffffffu, sum1, 2);
        l0 = l0 * corr0 + sum0;
        l1 = l1 * corr1 + sum1;
        mr0 = nm0; mr1 = nm1;

#pragma unroll
        for (int nt = 0; nt < 4; nt++) {
            oacc[nt][0] *= corr0; oacc[nt][1] *= corr0;
            oacc[nt][2] *= corr1; oacc[nt][3] *= corr1;
        }
        __syncwarp();

        // O += P @ V
        const uint32_t* Pu = reinterpret_cast<const uint32_t*>(Ps);
#pragma unroll
        for (int ks = 0; ks < 8; ks++) {
            int k0 = ks * 8;
            uint32_t a0 = Pu[(grp    ) * 68 + k0 + tig    ];
            uint32_t a1 = Pu[(grp + 8) * 68 + k0 + tig    ];
            uint32_t a2 = Pu[(grp    ) * 68 + k0 + tig + 4];
            uint32_t a3 = Pu[(grp + 8) * 68 + k0 + tig + 4];
#pragma unroll
            for (int nt = 0; nt < 4; nt++) {
                uint32_t b0 = f2tf(Vd[(k0 + tig    ) * 40 + nt * 8 + grp]);
                uint32_t b1 = f2tf(Vd[(k0 + tig + 4) * 40 + nt * 8 + grp]);
                mma_tf32(oacc[nt][0], oacc[nt][1], oacc[nt][2], oacc[nt][3],
                         a0, a1, a2, a3, b0, b1);
            }
        }
        __syncthreads();
    }

    float inv0 = 1.f / l0, inv1 = 1.f / l1;
    float* Ob = O + (brow + q0) * DIMC + h * HEAD_DIM;
#pragma unroll
    for (int nt = 0; nt < 4; nt++) {
        int c = nt * 8 + 2 * tig;
        *reinterpret_cast<float2*>(&Ob[(size_t)(grp    ) * DIMC + c]) =
            make_float2(oacc[nt][0] * inv0, oacc[nt][1] * inv0);
        *reinterpret_cast<float2*>(&Ob[(size_t)(grp + 8) * DIMC + c]) =
            make_float2(oacc[nt][2] * inv1, oacc[nt][3] * inv1);
    }
}

// ---------------------------------------------------------------------------
// Launch
// ---------------------------------------------------------------------------
extern "C" void kernel_launch(void* const* d_in, const int* in_sizes, int n_in,
                              void* d_out, int out_size)
{
    const float* x0      = (const float*)d_in[0];
    const float* x1      = (const float*)d_in[1];
    const float* qk_w    = (const float*)d_in[2];
    const float* v_w     = (const float*)d_in[3];
    const float* merge_w = (const float*)d_in[4];
    const float* ln1_w   = (const float*)d_in[5];
    const float* ln1_b   = (const float*)d_in[6];
    const float* ln2_w   = (const float*)d_in[7];
    const float* ln2_b   = (const float*)d_in[8];
    const float* fc1_w   = (const float*)d_in[9];
    const float* fc1_b   = (const float*)d_in[10];
    const float* fc2_w   = (const float*)d_in[11];
    const float* fc2_b   = (const float*)d_in[12];
    const float* gamma   = (const float*)d_in[13];
    float* out = (float*)d_out;

    float *nbuf, *qk, *v, *m, *mm, *h, *t;
    cudaGetSymbolAddress((void**)&nbuf, g_n);
    cudaGetSymbolAddress((void**)&qk,   g_qk);
    cudaGetSymbolAddress((void**)&v,    g_v);
    cudaGetSymbolAddress((void**)&m,    g_m);
    cudaGetSymbolAddress((void**)&mm,   g_mm);
    cudaGetSymbolAddress((void**)&h,    g_h);
    cudaGetSymbolAddress((void**)&t,    g_t);

    // opt-in dynamic smem (> 48 KB)
    cudaFuncSetAttribute(gemm_tc<false, false, true, false>,
                         cudaFuncAttributeMaxDynamicSharedMemorySize, GEMM_SMEM);
    cudaFuncSetAttribute(gemm_tc<false, false, false, false>,
                         cudaFuncAttributeMaxDynamicSharedMemorySize, GEMM_SMEM);
    cudaFuncSetAttribute(gemm_tc<true, true, false, true>,
                         cudaFuncAttributeMaxDynamicSharedMemorySize, GEMM_SMEM);
    cudaFuncSetAttribute(gemm_tc<false, true, false, false>,
                         cudaFuncAttributeMaxDynamicSharedMemorySize, GEMM_SMEM);
    cudaFuncSetAttribute(flash_tc,
                         cudaFuncAttributeMaxDynamicSharedMemorySize, FLASH_SMEM);

    // 1. LayerNorm1 (both streams, one launch)
    ln_kernel<<<TOTAL_ROWS / 8, 256>>>(x0, x1, ln1_w, ln1_b, nbuf);

    // 2. Fused qk+v projection (dual-output GEMM, 256 CTAs)
    dim3 gP2(2 * DIMC / 128, TOTAL_ROWS / 128);
    gemm_tc<false, false, true, false><<<gP2, 256, GEMM_SMEM>>>(
        nbuf, nullptr, nullptr, qk_w, v_w, nullptr, qk, v,
        DIMC, DIMC, QK_SCALE, 1.f);

    // 3. Flash attention, both directions in one launch
    dim3 gF(SEQ / 64, HEADS, 2 * BATCH);
    flash_tc<<<gF, 128, FLASH_SMEM>>>(qk, v, m);

    // 4. Merge projection
    dim3 gP(DIMC / 128, TOTAL_ROWS / 128);
    gemm_tc<false, false, false, false><<<gP, 256, GEMM_SMEM>>>(
        m, nullptr, nullptr, merge_w, nullptr, nullptr, mm, nullptr,
        DIMC, DIMC, 1.f, 1.f);

    // 5. fc1 + exact GELU, concat fused into A loader
    dim3 gF1(HIDDEN / 128, TOTAL_ROWS / 128);
    gemm_tc<true, true, false, true><<<gF1, 256, GEMM_SMEM>>>(
        x0, x1, mm, fc1_w, nullptr, fc1_b, h, nullptr,
        HIDDEN, 2 * DIMC, 1.f, 1.f);

    // 6. fc2
    gemm_tc<false, true, false, false><<<gP, 256, GEMM_SMEM>>>(
        h, nullptr, nullptr, fc2_w, nullptr, fc2_b, t, nullptr,
        DIMC, HIDDEN, 1.f, 1.f);

    // 7. Residual + gamma * LN2 (both streams)
    final_kernel<<<TOTAL_ROWS / 8, 256>>>(t, x0, x1, ln2_w, ln2_b, gamma, out);
}